// round 14
// baseline (speedup 1.0000x reference)
#include <cuda_runtime.h>
#include <cuda_bf16.h>
#include <stdint.h>
#include <math.h>

#define BSZ   4096
#define NND   32
#define ZDIM  128
#define HID   256
#define INF   64
#define TB    16
#define NTHR  256
#define NCTA  (BSZ / TB)

#define ZST   132
#define GST   65
#define TROW  528           // bytes per activation-tile row (264 bf16, conflict-free)

// dynamic smem byte offsets (TB=16)
#define OFF_ZBUF  0         // 16*132*4 = 8448 B
#define OFF_INVM  8448      // 128 B
#define OFF_GBUF  8576      // 16*65*4 = 4160 B
#define OFF_T0H   12736     // 16*528 = 8448 B each tile
#define OFF_T0L   21184
#define OFF_T1H   29632
#define OFF_T1L   38080
#define OFF_SCR   46528     // 12*512*4 = 24576 B (solve scratch)
#define SMEM_BYTES 71104

// ---------------- pre-packed weight fragments (B operand of m16n8k16) ----
// layout [ntile][kstep][lane] : uint4 {h0, h1, l0, l1}
__device__ uint4 g_f0[32 * 4 * 32];    // L0 fwd: B[k][f] = W0[k][f], K=64
__device__ uint4 g_f1[32 * 16 * 32];   // L1 fwd: W1[k][f]
__device__ uint4 g_f2[32 * 16 * 32];   // L2 fwd: W2[k][f]
__device__ uint4 g_b2[32 * 16 * 32];   // B1 bwd: B[j][f] = W2[f][j]
__device__ uint4 g_b1[32 * 16 * 32];   // B2 bwd: B[j][f] = W1[f][j]
__device__ uint4 g_b0[8 * 16 * 32];    // B3 bwd: B[j][m] = W0[m][j], N=64

__device__ __forceinline__ uint32_t pkbf2(float lo, float hi) {
    uint32_t r;
    asm("cvt.rn.bf16x2.f32 %0, %1, %2;" : "=r"(r) : "f"(hi), "f"(lo));
    return r;
}
__device__ __forceinline__ float bfhi(float x) {
    return __bfloat162float(__float2bfloat16(x));
}
__device__ __forceinline__ uint4 mkfrag(float a0, float a1, float a2, float a3) {
    uint4 q;
    q.x = pkbf2(a0, a1);
    q.y = pkbf2(a2, a3);
    q.z = pkbf2(a0 - bfhi(a0), a1 - bfhi(a1));
    q.w = pkbf2(a2 - bfhi(a2), a3 - bfhi(a3));
    return q;
}

__global__ void prep_k(const float* __restrict__ W0,
                       const float* __restrict__ W1,
                       const float* __restrict__ W2)
{
    int i = blockIdx.x * blockDim.x + threadIdx.x;    // 0..16383
    if (i >= 16384) return;
    int lane = i & 31, ks = (i >> 5) & 15, nt = i >> 9;
    int t = lane & 3, g = lane >> 2;
    int k0 = ks * 16, f0 = nt * 8;

    g_f1[i] = mkfrag(W1[(k0+2*t)*HID + f0+g],   W1[(k0+2*t+1)*HID + f0+g],
                     W1[(k0+2*t+8)*HID + f0+g], W1[(k0+2*t+9)*HID + f0+g]);
    g_f2[i] = mkfrag(W2[(k0+2*t)*HID + f0+g],   W2[(k0+2*t+1)*HID + f0+g],
                     W2[(k0+2*t+8)*HID + f0+g], W2[(k0+2*t+9)*HID + f0+g]);
    g_b1[i] = mkfrag(W1[(f0+g)*HID + k0+2*t],   W1[(f0+g)*HID + k0+2*t+1],
                     W1[(f0+g)*HID + k0+2*t+8], W1[(f0+g)*HID + k0+2*t+9]);
    g_b2[i] = mkfrag(W2[(f0+g)*HID + k0+2*t],   W2[(f0+g)*HID + k0+2*t+1],
                     W2[(f0+g)*HID + k0+2*t+8], W2[(f0+g)*HID + k0+2*t+9]);
    if (ks < 4) {
        int idx = (nt * 4 + ks) * 32 + lane;
        g_f0[idx] = mkfrag(W0[(k0+2*t)*HID + f0+g],   W0[(k0+2*t+1)*HID + f0+g],
                           W0[(k0+2*t+8)*HID + f0+g], W0[(k0+2*t+9)*HID + f0+g]);
    }
    if (nt < 8) {
        g_b0[i] = mkfrag(W0[(f0+g)*HID + k0+2*t],   W0[(f0+g)*HID + k0+2*t+1],
                         W0[(f0+g)*HID + k0+2*t+8], W0[(f0+g)*HID + k0+2*t+9]);
    }
}

// ---------------- mma / ldmatrix helpers ----------------
__device__ __forceinline__ uint32_t smem_u32(const void* p) {
    uint32_t a;
    asm("{ .reg .u64 t; cvta.to.shared.u64 t, %1; cvt.u32.u64 %0, t; }" : "=r"(a) : "l"(p));
    return a;
}
__device__ __forceinline__ void ldm4(uint32_t r[4], uint32_t addr) {
    asm volatile("ldmatrix.sync.aligned.m8n8.x4.shared.b16 {%0,%1,%2,%3}, [%4];"
        : "=r"(r[0]), "=r"(r[1]), "=r"(r[2]), "=r"(r[3]) : "r"(addr));
}
__device__ __forceinline__ void mma16(float c[4], const uint32_t a[4],
                                      uint32_t b0, uint32_t b1) {
    asm volatile("mma.sync.aligned.m16n8k16.row.col.f32.bf16.bf16.f32 "
        "{%0,%1,%2,%3}, {%4,%5,%6,%7}, {%8,%9}, {%0,%1,%2,%3};"
        : "+f"(c[0]), "+f"(c[1]), "+f"(c[2]), "+f"(c[3])
        : "r"(a[0]), "r"(a[1]), "r"(a[2]), "r"(a[3]), "r"(b0), "r"(b1));
}

// 3-term split-bf16 GEMM (forward layers): A hi/lo, B hi/lo
// NOTE (R9/R12 lesson): 12 mma per ks is the minimum compute density that
// hides the 4 fragment LDG.128s — do not thin this loop.
__device__ __forceinline__ void gemm_layer(float c[4][4],
    uint32_t tH, uint32_t tL, const uint4* __restrict__ wf,
    int ksteps, uint32_t abase, int ng, int lane)
{
    #pragma unroll
    for (int j = 0; j < 4; j++)
        #pragma unroll
        for (int q = 0; q < 4; q++) c[j][q] = 0.f;
    for (int ks = 0; ks < ksteps; ks++) {
        uint32_t ah[4], al[4];
        ldm4(ah, tH + abase + ks * 32);
        ldm4(al, tL + abase + ks * 32);
        #pragma unroll
        for (int j = 0; j < 4; j++) {
            uint4 b = wf[((ng * 4 + j) * ksteps + ks) * 32 + lane];
            mma16(c[j], ah, b.x, b.y);   // Ah * Bh
            mma16(c[j], ah, b.z, b.w);   // Ah * Bl
            mma16(c[j], al, b.x, b.y);   // Al * Bh
        }
    }
}

// 2-term GEMM (backward layers): A single-bf16 (hi tile only), B hi/lo
__device__ __forceinline__ void gemm_layer_hi(float c[4][4],
    uint32_t tH, const uint4* __restrict__ wf,
    int ksteps, uint32_t abase, int ng, int lane)
{
    #pragma unroll
    for (int j = 0; j < 4; j++)
        #pragma unroll
        for (int q = 0; q < 4; q++) c[j][q] = 0.f;
    for (int ks = 0; ks < ksteps; ks++) {
        uint32_t ah[4];
        ldm4(ah, tH + abase + ks * 32);
        #pragma unroll
        for (int j = 0; j < 4; j++) {
            uint4 b = wf[((ng * 4 + j) * ksteps + ks) * 32 + lane];
            mma16(c[j], ah, b.x, b.y);   // A * Bh
            mma16(c[j], ah, b.z, b.w);   // A * Bl
        }
    }
}

// store a (f, f+1) value pair as hi/lo bf16 into activation tile
__device__ __forceinline__ void split_st(char* th, char* tl, int s, int fc,
                                         float x, float y) {
    uint32_t off = (uint32_t)s * TROW + (uint32_t)fc * 2;
    *(uint32_t*)(th + off) = pkbf2(x, y);
    *(uint32_t*)(tl + off) = pkbf2(x - bfhi(x), y - bfhi(y));
}
// hi-only variant (backward activations)
__device__ __forceinline__ void st_hi(char* th, int s, int fc, float x, float y) {
    *(uint32_t*)(th + (uint32_t)s * TROW + (uint32_t)fc * 2) = pkbf2(x, y);
}

__device__ __forceinline__ void act2(float a, float& sp, float& sg) {
    float e = __expf(-fabsf(a));
    float d = 1.0f + e;
    sp = fmaxf(a, 0.f) + __logf(d);
    sg = (a >= 0.f) ? __fdividef(1.0f, d) : __fdividef(e, d);
}

__global__ __launch_bounds__(NTHR, 2)
void chnn_kernel(const float* __restrict__ z,
                 const float* __restrict__ m_params,
                 const float* __restrict__ b0v, const float* __restrict__ b1v,
                 const float* __restrict__ b2v, const float* __restrict__ W3,
                 float* __restrict__ out)
{
    extern __shared__ char smc[];
    float* zbuf = (float*)(smc + OFF_ZBUF);
    float* invm = (float*)(smc + OFF_INVM);
    float* gbuf = (float*)(smc + OFF_GBUF);
    char* T0h = smc + OFF_T0H; char* T0l = smc + OFF_T0L;
    char* T1h = smc + OFF_T1H; char* T1l = smc + OFF_T1L;

    // dedicated solve scratch (no aliasing with tiles -> prework can overlap B3)
    float* scr = (float*)(smc + OFF_SCR);
    float* Ex  = scr + 0  * NND * TB;
    float* Ey  = scr + 1  * NND * TB;
    float* Edx = scr + 2  * NND * TB;
    float* Edy = scr + 3  * NND * TB;
    float* Vx  = scr + 4  * NND * TB;
    float* Vy  = scr + 5  * NND * TB;
    float* Dd  = scr + 6  * NND * TB;   // holds 1/dd after factorization
    float* Du  = scr + 7  * NND * TB;
    float* Dl  = scr + 8  * NND * TB;
    float* So  = scr + 9  * NND * TB;
    float* R0  = scr + 10 * NND * TB;
    float* R1  = scr + 11 * NND * TB;

    const int tid = threadIdx.x;
    const int wid = tid >> 5;
    const int lane = tid & 31;
    const int blk = blockIdx.x;
    const int t = lane & 3, g = lane >> 2;
    const int ng = wid;                // n-group: features ng*32..ng*32+31
    const int s0 = g;

    const uint32_t smb = smem_u32(smc);
    const uint32_t uT0h = smb + OFF_T0H, uT0l = smb + OFF_T0L;
    const uint32_t uT1h = smb + OFF_T1H, uT1l = smb + OFF_T1L;
    const uint32_t abase = (uint32_t)(lane & 15) * TROW + ((lane >> 4) << 4);

    // fused: load z tile + build r tile (L0 A operand) hi/lo + invm — one barrier
    const float* zg = z + (size_t)blk * TB * ZDIM;
    for (int i = tid; i < TB * ZDIM; i += NTHR) {
        int s = i >> 7, c2 = i & 127;
        float x = zg[i];
        zbuf[s * ZST + c2] = x;
        if (c2 < INF) {
            uint32_t off = (uint32_t)s * TROW + (uint32_t)c2 * 2;
            __nv_bfloat16 h = __float2bfloat16(x);
            *(__nv_bfloat16*)(T0h + off) = h;
            *(__nv_bfloat16*)(T0l + off) = __float2bfloat16(x - __bfloat162float(h));
        }
    }
    if (tid < NND) invm[tid] = __expf(-m_params[tid]);
    __syncthreads();

    float c[4][4], sA[4][4], sB[4][4];

    // ================= L0 (3-term): h0 -> T1, sig0 -> sA =================
    gemm_layer(c, uT0h, uT0l, g_f0, 4, abase, ng, lane);
    #pragma unroll
    for (int j = 0; j < 4; j++) {
        int fc = ng * 32 + j * 8 + 2 * t;
        float2 bb = *(const float2*)(b0v + fc);
        float sp0, sp1, sp2, sp3;
        act2(c[j][0] + bb.x, sp0, sA[j][0]);
        act2(c[j][1] + bb.y, sp1, sA[j][1]);
        act2(c[j][2] + bb.x, sp2, sA[j][2]);
        act2(c[j][3] + bb.y, sp3, sA[j][3]);
        split_st(T1h, T1l, s0,     fc, sp0, sp1);
        split_st(T1h, T1l, s0 + 8, fc, sp2, sp3);
    }
    __syncthreads();

    // ================= L1 (3-term): h1 -> T0, sig1 -> sB =================
    gemm_layer(c, uT1h, uT1l, g_f1, 16, abase, ng, lane);
    #pragma unroll
    for (int j = 0; j < 4; j++) {
        int fc = ng * 32 + j * 8 + 2 * t;
        float2 bb = *(const float2*)(b1v + fc);
        float sp0, sp1, sp2, sp3;
        act2(c[j][0] + bb.x, sp0, sB[j][0]);
        act2(c[j][1] + bb.y, sp1, sB[j][1]);
        act2(c[j][2] + bb.x, sp2, sB[j][2]);
        act2(c[j][3] + bb.y, sp3, sB[j][3]);
        split_st(T0h, T0l, s0,     fc, sp0, sp1);
        split_st(T0h, T0l, s0 + 8, fc, sp2, sp3);
    }
    __syncthreads();

    // ================= L2 (3-term): da2 = W3[f]*sigmoid(a2) -> T1 (hi only) =================
    gemm_layer(c, uT0h, uT0l, g_f2, 16, abase, ng, lane);
    #pragma unroll
    for (int j = 0; j < 4; j++) {
        int fc = ng * 32 + j * 8 + 2 * t;
        float2 bb = *(const float2*)(b2v + fc);
        float2 w3 = *(const float2*)(W3 + fc);
        float v[4];
        #pragma unroll
        for (int q = 0; q < 4; q++) {
            float a = c[j][q] + ((q & 1) ? bb.y : bb.x);
            float e = __expf(-fabsf(a));
            float d = 1.0f + e;
            float sg = (a >= 0.f) ? __fdividef(1.0f, d) : __fdividef(e, d);
            v[q] = ((q & 1) ? w3.y : w3.x) * sg;
        }
        st_hi(T1h, s0,     fc, v[0], v[1]);
        st_hi(T1h, s0 + 8, fc, v[2], v[3]);
    }
    __syncthreads();

    // ================= B1 (2-term): da1 = (da2 @ W2^T) * sig1 -> T0 (hi only) =================
    gemm_layer_hi(c, uT1h, g_b2, 16, abase, ng, lane);
    #pragma unroll
    for (int j = 0; j < 4; j++) {
        int fc = ng * 32 + j * 8 + 2 * t;
        st_hi(T0h, s0,     fc, c[j][0] * sB[j][0], c[j][1] * sB[j][1]);
        st_hi(T0h, s0 + 8, fc, c[j][2] * sB[j][2], c[j][3] * sB[j][3]);
    }
    __syncthreads();

    // ================= B2 (2-term): da0 = (da1 @ W1^T) * sig0 -> T1 (hi only) =================
    gemm_layer_hi(c, uT0h, g_b1, 16, abase, ng, lane);
    #pragma unroll
    for (int j = 0; j < 4; j++) {
        int fc = ng * 32 + j * 8 + 2 * t;
        st_hi(T1h, s0,     fc, c[j][0] * sA[j][0], c[j][1] * sA[j][1]);
        st_hi(T1h, s0 + 8, fc, c[j][2] * sA[j][2], c[j][3] * sA[j][3]);
    }
    __syncthreads();

    // ===== B3 (warps 1-7) OVERLAPPED with g-independent solve prework (warp 0) =====
    if (wid >= 1) {
        // 8 n-tiles over 7 warps: warp 1 takes tiles 0 and 7
        for (int ntb = wid - 1; ntb < 8; ntb += 7) {
            float cg[4] = {0.f, 0.f, 0.f, 0.f};
            for (int ks = 0; ks < 16; ks++) {
                uint32_t ah[4];
                ldm4(ah, uT1h + abase + ks * 32);
                uint4 b = g_b0[(ntb * 16 + ks) * 32 + lane];
                mma16(cg, ah, b.x, b.y);
                mma16(cg, ah, b.z, b.w);
            }
            int fm = ntb * 8 + 2 * t;
            gbuf[g * GST + fm]           = cg[0];
            gbuf[g * GST + fm + 1]       = cg[1];
            gbuf[(g + 8) * GST + fm]     = cg[2];
            gbuf[(g + 8) * GST + fm + 1] = cg[3];
        }
    } else if (lane < TB) {
        const int s = lane;
        const float* zr = zbuf + s * ZST;
        // build E_c, Edot_c, v
        {
            float prx = zr[0], pry = zr[1];
            float im  = invm[0];
            float pvx = zr[64] * im, pvy = zr[65] * im;
            Ex[s]  = 2.f * prx;  Ey[s]  = 2.f * pry;
            Edx[s] = 2.f * pvx;  Edy[s] = 2.f * pvy;
            Vx[s] = pvx; Vy[s] = pvy;
            for (int cc = 1; cc < NND; cc++) {
                float rx = zr[2*cc], ry = zr[2*cc+1];
                float imc = invm[cc];
                float vx = zr[64 + 2*cc] * imc, vy = zr[65 + 2*cc] * imc;
                Ex[cc*TB+s]  = 2.f*(prx - rx);  Ey[cc*TB+s]  = 2.f*(pry - ry);
                Edx[cc*TB+s] = 2.f*(pvx - vx);  Edy[cc*TB+s] = 2.f*(pvy - vy);
                Vx[cc*TB+s] = vx; Vy[cc*TB+s] = vy;
                prx = rx; pry = ry; pvx = vx; pvy = vy;
            }
        }
        // tridiagonal G (Dd/Du), S offdiag (So), rhs b0 (R0) — no gbuf needed
        {
            float e0x = Ex[s],  e0y = Ey[s];
            float d0x = Edx[s], d0y = Edy[s];
            float im0 = invm[0];
            float e1x = Ex[TB+s],  e1y = Ey[TB+s];
            float d1x = Edx[TB+s], d1y = Edy[TB+s];
            Dd[s] = im0 * (e0x*e0x + e0y*e0y);
            Du[s] = im0 * (e0x*e1x + e0y*e1y);
            So[s] = im0 * (d0x*e1x + d0y*e1y - d1x*e0x - d1y*e0y);
            R0[s] = e0x*Vx[s] + e0y*Vy[s];
            for (int cc = 1; cc < NND; cc++) {
                float ecx = Ex[cc*TB+s],  ecy = Ey[cc*TB+s];
                float dcx = Edx[cc*TB+s], dcy = Edy[cc*TB+s];
                float imc = invm[cc], imp = invm[cc-1];
                Dd[cc*TB+s] = (imp + imc) * (ecx*ecx + ecy*ecy);
                R0[cc*TB+s] = 0.5f * (ecx*dcx + ecy*dcy);
                if (cc < NND - 1) {
                    float enx = Ex[(cc+1)*TB+s],  eny = Ey[(cc+1)*TB+s];
                    float dnx = Edx[(cc+1)*TB+s], dny = Edy[(cc+1)*TB+s];
                    Du[cc*TB+s] = -imc * (ecx*enx + ecy*eny);
                    So[cc*TB+s] =  imc * (dnx*ecx + dny*ecy - dcx*enx - dcy*eny);
                }
            }
        }
        // Thomas factorization with reciprocals (Dd <- 1/dd)
        {
            float rd = __fdividef(1.0f, Dd[s]);
            Dd[s] = rd;
            for (int cc = 1; cc < NND; cc++) {
                float du = Du[(cc-1)*TB+s];
                float l = du * rd;
                Dl[cc*TB+s] = l;
                float dd = Dd[cc*TB+s] - l * du;
                rd = __fdividef(1.0f, dd);
                Dd[cc*TB+s] = rd;
            }
        }
        // solve G x1 = b0 (in place in R0)
        for (int cc = 1; cc < NND; cc++)
            R0[cc*TB+s] -= Dl[cc*TB+s] * R0[(cc-1)*TB+s];
        R0[(NND-1)*TB+s] *= Dd[(NND-1)*TB+s];
        for (int cc = NND - 2; cc >= 0; cc--)
            R0[cc*TB+s] = (R0[cc*TB+s] - Du[cc*TB+s] * R0[(cc+1)*TB+s]) * Dd[cc*TB+s];
    }
    __syncthreads();

    // ===== fused parallel pass: b1 (registers) then y = S x1 - b1 -> R1 =====
    for (int idx = tid; idx < NND * TB; idx += NTHR) {
        int s = idx & (TB - 1), cc = idx >> 4;
        float b1val;
        if (cc == 0) {
            float e0x = Ex[s],  e0y = Ey[s];
            float d0x = Edx[s], d0y = Edy[s];
            float im0 = invm[0];
            float g0x = gbuf[s*GST + 0], g0y = gbuf[s*GST + 1];
            b1val = d0x*Vx[s] + d0y*Vy[s] - im0*(e0x*g0x + e0y*g0y);
        } else {
            float ecx = Ex[cc*TB+s],  ecy = Ey[cc*TB+s];
            float dcx = Edx[cc*TB+s], dcy = Edy[cc*TB+s];
            float imc = invm[cc], imp = invm[cc-1];
            float gpx = gbuf[s*GST + 2*(cc-1)], gpy = gbuf[s*GST + 2*(cc-1)+1];
            float gcx = gbuf[s*GST + 2*cc],     gcy = gbuf[s*GST + 2*cc+1];
            b1val = 0.5f*(dcx*dcx + dcy*dcy)
                  - (ecx*(imp*gpx - imc*gcx) + ecy*(imp*gpy - imc*gcy));
        }
        float y;
        if (cc == 0)
            y = So[s] * R0[TB+s] - b1val;
        else if (cc < NND - 1)
            y = So[cc*TB+s]*R0[(cc+1)*TB+s] - So[(cc-1)*TB+s]*R0[(cc-1)*TB+s] - b1val;
        else
            y = -So[(NND-2)*TB+s]*R0[(NND-2)*TB+s] - b1val;
        R1[cc*TB+s] = y;
    }
    __syncthreads();

    // ===== serial x0 Thomas substitution (16 lanes) =====
    if (tid < TB) {
        const int s = tid;
        for (int cc = 1; cc < NND; cc++)
            R1[cc*TB+s] -= Dl[cc*TB+s] * R1[(cc-1)*TB+s];
        R1[(NND-1)*TB+s] *= Dd[(NND-1)*TB+s];
        for (int cc = NND - 2; cc >= 0; cc--)
            R1[cc*TB+s] = (R1[cc*TB+s] - Du[cc*TB+s]*R1[(cc+1)*TB+s]) * Dd[cc*TB+s];
    }
    __syncthreads();

    // ===== parallel output assembly with DIRECT coalesced global store =====
    // thread -> (s = tid>>4, i-pair = (tid&15)*2 + {0,1}); two STG.128 per thread
    {
        const int s = tid >> 4;
        float* og = out + (size_t)blk * TB * ZDIM + s * ZDIM;
        float vr[4], vp[4];
        #pragma unroll
        for (int ii = 0; ii < 2; ii++) {
            int i = (tid & 15) * 2 + ii;
            float eix = Ex[i*TB+s],  eiy = Ey[i*TB+s];
            float dix = Edx[i*TB+s], diy = Edy[i*TB+s];
            float x1i = R0[i*TB+s],  x0i = R1[i*TB+s];
            float p1x, p1y, p0x, p0y, pdx, pdy;
            if (i == 0) {
                float enx = Ex[TB+s],  eny = Ey[TB+s];
                float dnx = Edx[TB+s], dny = Edy[TB+s];
                float x1n = R0[TB+s],  x0n = R1[TB+s];
                p1x = eix*x1i + enx*x1n;  p1y = eiy*x1i + eny*x1n;
                p0x = eix*x0i + enx*x0n;  p0y = eiy*x0i + eny*x0n;
                pdx = dix*x1i + dnx*x1n;  pdy = diy*x1i + dny*x1n;
            } else if (i < NND - 1) {
                float enx = Ex[(i+1)*TB+s],  eny = Ey[(i+1)*TB+s];
                float dnx = Edx[(i+1)*TB+s], dny = Edy[(i+1)*TB+s];
                float x1n = R0[(i+1)*TB+s],  x0n = R1[(i+1)*TB+s];
                p1x = -eix*x1i + enx*x1n;  p1y = -eiy*x1i + eny*x1n;
                p0x = -eix*x0i + enx*x0n;  p0y = -eiy*x0i + eny*x0n;
                pdx = -dix*x1i + dnx*x1n;  pdy = -diy*x1i + dny*x1n;
            } else {
                p1x = -eix*x1i; p1y = -eiy*x1i;
                p0x = -eix*x0i; p0y = -eiy*x0i;
                pdx = -dix*x1i; pdy = -diy*x1i;
            }
            float imi = invm[i];
            float gx = gbuf[s*GST + 2*i], gy = gbuf[s*GST + 2*i + 1];
            vr[2*ii]     = Vx[i*TB+s] - imi * p1x;
            vr[2*ii + 1] = Vy[i*TB+s] - imi * p1y;
            vp[2*ii]     = -gx + p0x + pdx;
            vp[2*ii + 1] = -gy + p0y + pdy;
        }
        int base = (tid & 15) * 4;
        *(float4*)(og + base)      = make_float4(vr[0], vr[1], vr[2], vr[3]);
        *(float4*)(og + 64 + base) = make_float4(vp[0], vp[1], vp[2], vp[3]);
    }
}

extern "C" void kernel_launch(void* const* d_in, const int* in_sizes, int n_in,
                              void* d_out, int out_size)
{
    (void)in_sizes; (void)n_in; (void)out_size;
    const float* z  = (const float*)d_in[1];
    const float* mp = (const float*)d_in[2];
    const float* W0 = (const float*)d_in[3];
    const float* b0 = (const float*)d_in[4];
    const float* W1 = (const float*)d_in[5];
    const float* b1 = (const float*)d_in[6];
    const float* W2 = (const float*)d_in[7];
    const float* b2 = (const float*)d_in[8];
    const float* W3 = (const float*)d_in[9];
    float* out = (float*)d_out;

    prep_k<<<64, 256>>>(W0, W1, W2);

    cudaFuncSetAttribute(chnn_kernel, cudaFuncAttributeMaxDynamicSharedMemorySize,
                         SMEM_BYTES);
    chnn_kernel<<<NCTA, NTHR, SMEM_BYTES>>>(z, mp, b0, b1, b2, W3, out);
}

// round 15
// speedup vs baseline: 1.0721x; 1.0721x over previous
#include <cuda_runtime.h>
#include <cuda_bf16.h>
#include <stdint.h>
#include <math.h>

#define BSZ   4096
#define NND   32
#define ZDIM  128
#define HID   256
#define INF   64
#define TB    16
#define NTHR  256
#define NCTA  (BSZ / TB)

#define ZST   132
#define GST   65
#define TROW  528           // bytes per activation-tile row (264 bf16, conflict-free)

// dynamic smem byte offsets (TB=16)
#define OFF_ZBUF  0         // 16*132*4 = 8448 B
#define OFF_INVM  8448      // 128 B
#define OFF_GBUF  8576      // 16*65*4 = 4160 B
#define OFF_T0H   12736     // 16*528 = 8448 B each tile
#define OFF_T0L   21184
#define OFF_T1H   29632
#define OFF_T1L   38080
#define OFF_SCR   46528     // 12*512*4 = 24576 B (solve scratch)
#define SMEM_BYTES 71104

// ---------------- pre-packed weight fragments (B operand of m16n8k16) ----
// layout [ntile][kstep][lane] : uint4 {h0, h1, l0, l1}
__device__ uint4 g_f0[32 * 4 * 32];    // L0 fwd: B[k][f] = W0[k][f], K=64
__device__ uint4 g_f1[32 * 16 * 32];   // L1 fwd: W1[k][f]
__device__ uint4 g_f2[32 * 16 * 32];   // L2 fwd: W2[k][f]
__device__ uint4 g_b2[32 * 16 * 32];   // B1 bwd: B[j][f] = W2[f][j]
__device__ uint4 g_b1[32 * 16 * 32];   // B2 bwd: B[j][f] = W1[f][j]
__device__ uint4 g_b0[8 * 16 * 32];    // B3 bwd: B[j][m] = W0[m][j], N=64

__device__ __forceinline__ uint32_t pkbf2(float lo, float hi) {
    uint32_t r;
    asm("cvt.rn.bf16x2.f32 %0, %1, %2;" : "=r"(r) : "f"(hi), "f"(lo));
    return r;
}
__device__ __forceinline__ float bfhi(float x) {
    return __bfloat162float(__float2bfloat16(x));
}
__device__ __forceinline__ uint4 mkfrag(float a0, float a1, float a2, float a3) {
    uint4 q;
    q.x = pkbf2(a0, a1);
    q.y = pkbf2(a2, a3);
    q.z = pkbf2(a0 - bfhi(a0), a1 - bfhi(a1));
    q.w = pkbf2(a2 - bfhi(a2), a3 - bfhi(a3));
    return q;
}

__global__ void prep_k(const float* __restrict__ W0,
                       const float* __restrict__ W1,
                       const float* __restrict__ W2)
{
    int i = blockIdx.x * blockDim.x + threadIdx.x;    // 0..16383
    if (i >= 16384) return;
    int lane = i & 31, ks = (i >> 5) & 15, nt = i >> 9;
    int t = lane & 3, g = lane >> 2;
    int k0 = ks * 16, f0 = nt * 8;

    g_f1[i] = mkfrag(W1[(k0+2*t)*HID + f0+g],   W1[(k0+2*t+1)*HID + f0+g],
                     W1[(k0+2*t+8)*HID + f0+g], W1[(k0+2*t+9)*HID + f0+g]);
    g_f2[i] = mkfrag(W2[(k0+2*t)*HID + f0+g],   W2[(k0+2*t+1)*HID + f0+g],
                     W2[(k0+2*t+8)*HID + f0+g], W2[(k0+2*t+9)*HID + f0+g]);
    g_b1[i] = mkfrag(W1[(f0+g)*HID + k0+2*t],   W1[(f0+g)*HID + k0+2*t+1],
                     W1[(f0+g)*HID + k0+2*t+8], W1[(f0+g)*HID + k0+2*t+9]);
    g_b2[i] = mkfrag(W2[(f0+g)*HID + k0+2*t],   W2[(f0+g)*HID + k0+2*t+1],
                     W2[(f0+g)*HID + k0+2*t+8], W2[(f0+g)*HID + k0+2*t+9]);
    if (ks < 4) {
        int idx = (nt * 4 + ks) * 32 + lane;
        g_f0[idx] = mkfrag(W0[(k0+2*t)*HID + f0+g],   W0[(k0+2*t+1)*HID + f0+g],
                           W0[(k0+2*t+8)*HID + f0+g], W0[(k0+2*t+9)*HID + f0+g]);
    }
    if (nt < 8) {
        g_b0[i] = mkfrag(W0[(f0+g)*HID + k0+2*t],   W0[(f0+g)*HID + k0+2*t+1],
                         W0[(f0+g)*HID + k0+2*t+8], W0[(f0+g)*HID + k0+2*t+9]);
    }
}

// ---------------- mma / ldmatrix helpers ----------------
__device__ __forceinline__ uint32_t smem_u32(const void* p) {
    uint32_t a;
    asm("{ .reg .u64 t; cvta.to.shared.u64 t, %1; cvt.u32.u64 %0, t; }" : "=r"(a) : "l"(p));
    return a;
}
__device__ __forceinline__ void ldm4(uint32_t r[4], uint32_t addr) {
    asm volatile("ldmatrix.sync.aligned.m8n8.x4.shared.b16 {%0,%1,%2,%3}, [%4];"
        : "=r"(r[0]), "=r"(r[1]), "=r"(r[2]), "=r"(r[3]) : "r"(addr));
}
__device__ __forceinline__ void mma16(float c[4], const uint32_t a[4],
                                      uint32_t b0, uint32_t b1) {
    asm volatile("mma.sync.aligned.m16n8k16.row.col.f32.bf16.bf16.f32 "
        "{%0,%1,%2,%3}, {%4,%5,%6,%7}, {%8,%9}, {%0,%1,%2,%3};"
        : "+f"(c[0]), "+f"(c[1]), "+f"(c[2]), "+f"(c[3])
        : "r"(a[0]), "r"(a[1]), "r"(a[2]), "r"(a[3]), "r"(b0), "r"(b1));
}

// 3-term split-bf16 GEMM (forward layers): A hi/lo, B hi/lo
// NOTE (R9/R12 lesson): 12 mma per ks is the minimum compute density that
// hides the 4 fragment LDG.128s — do not thin this loop.
__device__ __forceinline__ void gemm_layer(float c[4][4],
    uint32_t tH, uint32_t tL, const uint4* __restrict__ wf,
    int ksteps, uint32_t abase, int ng, int lane)
{
    #pragma unroll
    for (int j = 0; j < 4; j++)
        #pragma unroll
        for (int q = 0; q < 4; q++) c[j][q] = 0.f;
    for (int ks = 0; ks < ksteps; ks++) {
        uint32_t ah[4], al[4];
        ldm4(ah, tH + abase + ks * 32);
        ldm4(al, tL + abase + ks * 32);
        #pragma unroll
        for (int j = 0; j < 4; j++) {
            uint4 b = wf[((ng * 4 + j) * ksteps + ks) * 32 + lane];
            mma16(c[j], ah, b.x, b.y);   // Ah * Bh
            mma16(c[j], ah, b.z, b.w);   // Ah * Bl
            mma16(c[j], al, b.x, b.y);   // Al * Bh
        }
    }
}

// 2-term GEMM (backward layers): A single-bf16 (hi tile only), B hi/lo
__device__ __forceinline__ void gemm_layer_hi(float c[4][4],
    uint32_t tH, const uint4* __restrict__ wf,
    int ksteps, uint32_t abase, int ng, int lane)
{
    #pragma unroll
    for (int j = 0; j < 4; j++)
        #pragma unroll
        for (int q = 0; q < 4; q++) c[j][q] = 0.f;
    for (int ks = 0; ks < ksteps; ks++) {
        uint32_t ah[4];
        ldm4(ah, tH + abase + ks * 32);
        #pragma unroll
        for (int j = 0; j < 4; j++) {
            uint4 b = wf[((ng * 4 + j) * ksteps + ks) * 32 + lane];
            mma16(c[j], ah, b.x, b.y);   // A * Bh
            mma16(c[j], ah, b.z, b.w);   // A * Bl
        }
    }
}

// store a (f, f+1) value pair as hi/lo bf16 into activation tile
__device__ __forceinline__ void split_st(char* th, char* tl, int s, int fc,
                                         float x, float y) {
    uint32_t off = (uint32_t)s * TROW + (uint32_t)fc * 2;
    *(uint32_t*)(th + off) = pkbf2(x, y);
    *(uint32_t*)(tl + off) = pkbf2(x - bfhi(x), y - bfhi(y));
}
// hi-only variant (backward activations)
__device__ __forceinline__ void st_hi(char* th, int s, int fc, float x, float y) {
    *(uint32_t*)(th + (uint32_t)s * TROW + (uint32_t)fc * 2) = pkbf2(x, y);
}

__device__ __forceinline__ void act2(float a, float& sp, float& sg) {
    float e = __expf(-fabsf(a));
    float d = 1.0f + e;
    sp = fmaxf(a, 0.f) + __logf(d);
    sg = (a >= 0.f) ? __fdividef(1.0f, d) : __fdividef(e, d);
}

__global__ __launch_bounds__(NTHR, 2)
void chnn_kernel(const float* __restrict__ z,
                 const float* __restrict__ m_params,
                 const float* __restrict__ b0v, const float* __restrict__ b1v,
                 const float* __restrict__ b2v, const float* __restrict__ W3,
                 float* __restrict__ out)
{
    extern __shared__ char smc[];
    float* zbuf = (float*)(smc + OFF_ZBUF);
    float* invm = (float*)(smc + OFF_INVM);
    float* gbuf = (float*)(smc + OFF_GBUF);
    char* T0h = smc + OFF_T0H; char* T0l = smc + OFF_T0L;
    char* T1h = smc + OFF_T1H; char* T1l = smc + OFF_T1L;

    // dedicated solve scratch (no aliasing with tiles)
    float* scr = (float*)(smc + OFF_SCR);
    float* Ex  = scr + 0  * NND * TB;
    float* Ey  = scr + 1  * NND * TB;
    float* Edx = scr + 2  * NND * TB;
    float* Edy = scr + 3  * NND * TB;
    float* Vx  = scr + 4  * NND * TB;
    float* Vy  = scr + 5  * NND * TB;
    float* Dd  = scr + 6  * NND * TB;   // holds 1/dd after factorization
    float* Du  = scr + 7  * NND * TB;
    float* Dl  = scr + 8  * NND * TB;
    float* So  = scr + 9  * NND * TB;
    float* R0  = scr + 10 * NND * TB;
    float* R1  = scr + 11 * NND * TB;

    const int tid = threadIdx.x;
    const int wid = tid >> 5;
    const int lane = tid & 31;
    const int blk = blockIdx.x;
    const int t = lane & 3, g = lane >> 2;
    const int ng = wid;                // n-group: features ng*32..ng*32+31
    const int s0 = g;

    const uint32_t smb = smem_u32(smc);
    const uint32_t uT0h = smb + OFF_T0H, uT0l = smb + OFF_T0L;
    const uint32_t uT1h = smb + OFF_T1H, uT1l = smb + OFF_T1L;
    const uint32_t abase = (uint32_t)(lane & 15) * TROW + ((lane >> 4) << 4);

    // fused: load z tile + build r tile (L0 A operand) hi/lo + invm
    const float* zg = z + (size_t)blk * TB * ZDIM;
    for (int i = tid; i < TB * ZDIM; i += NTHR) {
        int s = i >> 7, c2 = i & 127;
        float x = zg[i];
        zbuf[s * ZST + c2] = x;
        if (c2 < INF) {
            uint32_t off = (uint32_t)s * TROW + (uint32_t)c2 * 2;
            __nv_bfloat16 h = __float2bfloat16(x);
            *(__nv_bfloat16*)(T0h + off) = h;
            *(__nv_bfloat16*)(T0l + off) = __float2bfloat16(x - __bfloat162float(h));
        }
    }
    if (tid < NND) invm[tid] = __expf(-m_params[tid]);
    __syncthreads();

    // ===== parallel E/Edot/v + G/S/b0 build: no loop-carry, 512 (s,cc) pairs =====
    for (int idx = tid; idx < NND * TB; idx += NTHR) {
        int s = idx & (TB - 1), cc = idx >> 4;
        const float* zr = zbuf + s * ZST;
        float imc = invm[cc];
        float rx = zr[2*cc], ry = zr[2*cc+1];
        float vx = zr[64 + 2*cc] * imc, vy = zr[65 + 2*cc] * imc;
        float ex, ey, edx, edy;
        if (cc == 0) {
            ex = 2.f * rx;  ey = 2.f * ry;
            edx = 2.f * vx; edy = 2.f * vy;
        } else {
            float imp = invm[cc-1];
            float px = zr[2*(cc-1)], py = zr[2*(cc-1)+1];
            float pvx = zr[64 + 2*(cc-1)] * imp, pvy = zr[65 + 2*(cc-1)] * imp;
            ex = 2.f * (px - rx);   ey = 2.f * (py - ry);
            edx = 2.f * (pvx - vx); edy = 2.f * (pvy - vy);
        }
        Ex[cc*TB+s] = ex;   Ey[cc*TB+s] = ey;
        Edx[cc*TB+s] = edx; Edy[cc*TB+s] = edy;
        Vx[cc*TB+s] = vx;   Vy[cc*TB+s] = vy;

        if (cc == 0) {
            Dd[s] = imc * (ex*ex + ey*ey);
            R0[s] = ex*vx + ey*vy;
        } else {
            Dd[cc*TB+s] = (invm[cc-1] + imc) * (ex*ex + ey*ey);
            R0[cc*TB+s] = 0.5f * (ex*edx + ey*edy);
        }
        if (cc < NND - 1) {
            // e_{cc+1}, ed_{cc+1} recomputed locally
            float imn = invm[cc+1];
            float nx = zr[2*(cc+1)], nyv = zr[2*(cc+1)+1];
            float nvx = zr[64 + 2*(cc+1)] * imn, nvy = zr[65 + 2*(cc+1)] * imn;
            float enx = 2.f * (rx - nx),  eny = 2.f * (ry - nyv);
            float dnx = 2.f * (vx - nvx), dny = 2.f * (vy - nvy);
            if (cc == 0) {
                Du[s] = imc * (ex*enx + ey*eny);
                So[s] = imc * (edx*enx + edy*eny - dnx*ex - dny*ey);
            } else {
                Du[cc*TB+s] = -imc * (ex*enx + ey*eny);
                So[cc*TB+s] =  imc * (dnx*ex + dny*ey - edx*enx - edy*eny);
            }
        }
    }
    __syncthreads();

    float c[4][4], sA[4][4], sB[4][4];

    // ================= L0 (3-term): h0 -> T1, sig0 -> sA =================
    gemm_layer(c, uT0h, uT0l, g_f0, 4, abase, ng, lane);
    #pragma unroll
    for (int j = 0; j < 4; j++) {
        int fc = ng * 32 + j * 8 + 2 * t;
        float2 bb = *(const float2*)(b0v + fc);
        float sp0, sp1, sp2, sp3;
        act2(c[j][0] + bb.x, sp0, sA[j][0]);
        act2(c[j][1] + bb.y, sp1, sA[j][1]);
        act2(c[j][2] + bb.x, sp2, sA[j][2]);
        act2(c[j][3] + bb.y, sp3, sA[j][3]);
        split_st(T1h, T1l, s0,     fc, sp0, sp1);
        split_st(T1h, T1l, s0 + 8, fc, sp2, sp3);
    }
    __syncthreads();

    // ================= L1 (3-term): h1 -> T0, sig1 -> sB =================
    gemm_layer(c, uT1h, uT1l, g_f1, 16, abase, ng, lane);
    #pragma unroll
    for (int j = 0; j < 4; j++) {
        int fc = ng * 32 + j * 8 + 2 * t;
        float2 bb = *(const float2*)(b1v + fc);
        float sp0, sp1, sp2, sp3;
        act2(c[j][0] + bb.x, sp0, sB[j][0]);
        act2(c[j][1] + bb.y, sp1, sB[j][1]);
        act2(c[j][2] + bb.x, sp2, sB[j][2]);
        act2(c[j][3] + bb.y, sp3, sB[j][3]);
        split_st(T0h, T0l, s0,     fc, sp0, sp1);
        split_st(T0h, T0l, s0 + 8, fc, sp2, sp3);
    }
    __syncthreads();

    // ================= L2 (3-term): da2 = W3[f]*sigmoid(a2) -> T1 (hi only) =================
    gemm_layer(c, uT0h, uT0l, g_f2, 16, abase, ng, lane);
    #pragma unroll
    for (int j = 0; j < 4; j++) {
        int fc = ng * 32 + j * 8 + 2 * t;
        float2 bb = *(const float2*)(b2v + fc);
        float2 w3 = *(const float2*)(W3 + fc);
        float v[4];
        #pragma unroll
        for (int q = 0; q < 4; q++) {
            float a = c[j][q] + ((q & 1) ? bb.y : bb.x);
            float e = __expf(-fabsf(a));
            float d = 1.0f + e;
            float sg = (a >= 0.f) ? __fdividef(1.0f, d) : __fdividef(e, d);
            v[q] = ((q & 1) ? w3.y : w3.x) * sg;
        }
        st_hi(T1h, s0,     fc, v[0], v[1]);
        st_hi(T1h, s0 + 8, fc, v[2], v[3]);
    }
    __syncthreads();

    // ================= B1 (2-term): da1 = (da2 @ W2^T) * sig1 -> T0 (hi only) =================
    gemm_layer_hi(c, uT1h, g_b2, 16, abase, ng, lane);
    #pragma unroll
    for (int j = 0; j < 4; j++) {
        int fc = ng * 32 + j * 8 + 2 * t;
        st_hi(T0h, s0,     fc, c[j][0] * sB[j][0], c[j][1] * sB[j][1]);
        st_hi(T0h, s0 + 8, fc, c[j][2] * sB[j][2], c[j][3] * sB[j][3]);
    }
    __syncthreads();

    // ================= B2 (2-term): da0 = (da1 @ W1^T) * sig0 -> T1 (hi only) =================
    gemm_layer_hi(c, uT0h, g_b1, 16, abase, ng, lane);
    #pragma unroll
    for (int j = 0; j < 4; j++) {
        int fc = ng * 32 + j * 8 + 2 * t;
        st_hi(T1h, s0,     fc, c[j][0] * sA[j][0], c[j][1] * sA[j][1]);
        st_hi(T1h, s0 + 8, fc, c[j][2] * sA[j][2], c[j][3] * sA[j][3]);
    }
    __syncthreads();

    // ===== B3 (warps 1-7) OVERLAPPED with serial-only solve prework (warp 0) =====
    if (wid >= 1) {
        // 8 n-tiles over 7 warps: warp 1 takes tiles 0 and 7
        for (int ntb = wid - 1; ntb < 8; ntb += 7) {
            float cg[4] = {0.f, 0.f, 0.f, 0.f};
            for (int ks = 0; ks < 16; ks++) {
                uint32_t ah[4];
                ldm4(ah, uT1h + abase + ks * 32);
                uint4 b = g_b0[(ntb * 16 + ks) * 32 + lane];
                mma16(cg, ah, b.x, b.y);
                mma16(cg, ah, b.z, b.w);
            }
            int fm = ntb * 8 + 2 * t;
            gbuf[g * GST + fm]           = cg[0];
            gbuf[g * GST + fm + 1]       = cg[1];
            gbuf[(g + 8) * GST + fm]     = cg[2];
            gbuf[(g + 8) * GST + fm + 1] = cg[3];
        }
    } else if (lane < TB) {
        const int s = lane;
        // Thomas factorization (reciprocal form) FUSED with x1 forward substitution
        {
            float rd = __fdividef(1.0f, Dd[s]);
            Dd[s] = rd;
            float r_prev = R0[s];
            for (int cc = 1; cc < NND; cc++) {
                float du = Du[(cc-1)*TB+s];
                float l = du * rd;
                Dl[cc*TB+s] = l;
                float dd = Dd[cc*TB+s] - l * du;
                rd = __fdividef(1.0f, dd);
                Dd[cc*TB+s] = rd;
                float r_cur = R0[cc*TB+s] - l * r_prev;
                R0[cc*TB+s] = r_cur;
                r_prev = r_cur;
            }
        }
        // x1 backward substitution
        R0[(NND-1)*TB+s] *= Dd[(NND-1)*TB+s];
        for (int cc = NND - 2; cc >= 0; cc--)
            R0[cc*TB+s] = (R0[cc*TB+s] - Du[cc*TB+s] * R0[(cc+1)*TB+s]) * Dd[cc*TB+s];
    }
    __syncthreads();

    // ===== fused parallel pass: b1 (registers) then y = S x1 - b1 -> R1 =====
    for (int idx = tid; idx < NND * TB; idx += NTHR) {
        int s = idx & (TB - 1), cc = idx >> 4;
        float b1val;
        if (cc == 0) {
            float e0x = Ex[s],  e0y = Ey[s];
            float d0x = Edx[s], d0y = Edy[s];
            float im0 = invm[0];
            float g0x = gbuf[s*GST + 0], g0y = gbuf[s*GST + 1];
            b1val = d0x*Vx[s] + d0y*Vy[s] - im0*(e0x*g0x + e0y*g0y);
        } else {
            float ecx = Ex[cc*TB+s],  ecy = Ey[cc*TB+s];
            float dcx = Edx[cc*TB+s], dcy = Edy[cc*TB+s];
            float imc = invm[cc], imp = invm[cc-1];
            float gpx = gbuf[s*GST + 2*(cc-1)], gpy = gbuf[s*GST + 2*(cc-1)+1];
            float gcx = gbuf[s*GST + 2*cc],     gcy = gbuf[s*GST + 2*cc+1];
            b1val = 0.5f*(dcx*dcx + dcy*dcy)
                  - (ecx*(imp*gpx - imc*gcx) + ecy*(imp*gpy - imc*gcy));
        }
        float y;
        if (cc == 0)
            y = So[s] * R0[TB+s] - b1val;
        else if (cc < NND - 1)
            y = So[cc*TB+s]*R0[(cc+1)*TB+s] - So[(cc-1)*TB+s]*R0[(cc-1)*TB+s] - b1val;
        else
            y = -So[(NND-2)*TB+s]*R0[(NND-2)*TB+s] - b1val;
        R1[cc*TB+s] = y;
    }
    __syncthreads();

    // ===== serial x0 Thomas substitution (16 lanes) =====
    if (tid < TB) {
        const int s = tid;
        for (int cc = 1; cc < NND; cc++)
            R1[cc*TB+s] -= Dl[cc*TB+s] * R1[(cc-1)*TB+s];
        R1[(NND-1)*TB+s] *= Dd[(NND-1)*TB+s];
        for (int cc = NND - 2; cc >= 0; cc--)
            R1[cc*TB+s] = (R1[cc*TB+s] - Du[cc*TB+s]*R1[(cc+1)*TB+s]) * Dd[cc*TB+s];
    }
    __syncthreads();

    // ===== parallel output assembly with DIRECT coalesced global store =====
    // thread -> (s = tid>>4, i-pair = (tid&15)*2 + {0,1}); two STG.128 per thread
    {
        const int s = tid >> 4;
        float* og = out + (size_t)blk * TB * ZDIM + s * ZDIM;
        float vr[4], vp[4];
        #pragma unroll
        for (int ii = 0; ii < 2; ii++) {
            int i = (tid & 15) * 2 + ii;
            float eix = Ex[i*TB+s],  eiy = Ey[i*TB+s];
            float dix = Edx[i*TB+s], diy = Edy[i*TB+s];
            float x1i = R0[i*TB+s],  x0i = R1[i*TB+s];
            float p1x, p1y, p0x, p0y, pdx, pdy;
            if (i == 0) {
                float enx = Ex[TB+s],  eny = Ey[TB+s];
                float dnx = Edx[TB+s], dny = Edy[TB+s];
                float x1n = R0[TB+s],  x0n = R1[TB+s];
                p1x = eix*x1i + enx*x1n;  p1y = eiy*x1i + eny*x1n;
                p0x = eix*x0i + enx*x0n;  p0y = eiy*x0i + eny*x0n;
                pdx = dix*x1i + dnx*x1n;  pdy = diy*x1i + dny*x1n;
            } else if (i < NND - 1) {
                float enx = Ex[(i+1)*TB+s],  eny = Ey[(i+1)*TB+s];
                float dnx = Edx[(i+1)*TB+s], dny = Edy[(i+1)*TB+s];
                float x1n = R0[(i+1)*TB+s],  x0n = R1[(i+1)*TB+s];
                p1x = -eix*x1i + enx*x1n;  p1y = -eiy*x1i + eny*x1n;
                p0x = -eix*x0i + enx*x0n;  p0y = -eiy*x0i + eny*x0n;
                pdx = -dix*x1i + dnx*x1n;  pdy = -diy*x1i + dny*x1n;
            } else {
                p1x = -eix*x1i; p1y = -eiy*x1i;
                p0x = -eix*x0i; p0y = -eiy*x0i;
                pdx = -dix*x1i; pdy = -diy*x1i;
            }
            float imi = invm[i];
            float gx = gbuf[s*GST + 2*i], gy = gbuf[s*GST + 2*i + 1];
            vr[2*ii]     = Vx[i*TB+s] - imi * p1x;
            vr[2*ii + 1] = Vy[i*TB+s] - imi * p1y;
            vp[2*ii]     = -gx + p0x + pdx;
            vp[2*ii + 1] = -gy + p0y + pdy;
        }
        int base = (tid & 15) * 4;
        *(float4*)(og + base)      = make_float4(vr[0], vr[1], vr[2], vr[3]);
        *(float4*)(og + 64 + base) = make_float4(vp[0], vp[1], vp[2], vp[3]);
    }
}

extern "C" void kernel_launch(void* const* d_in, const int* in_sizes, int n_in,
                              void* d_out, int out_size)
{
    (void)in_sizes; (void)n_in; (void)out_size;
    const float* z  = (const float*)d_in[1];
    const float* mp = (const float*)d_in[2];
    const float* W0 = (const float*)d_in[3];
    const float* b0 = (const float*)d_in[4];
    const float* W1 = (const float*)d_in[5];
    const float* b1 = (const float*)d_in[6];
    const float* W2 = (const float*)d_in[7];
    const float* b2 = (const float*)d_in[8];
    const float* W3 = (const float*)d_in[9];
    float* out = (float*)d_out;

    prep_k<<<64, 256>>>(W0, W1, W2);

    cudaFuncSetAttribute(chnn_kernel, cudaFuncAttributeMaxDynamicSharedMemorySize,
                         SMEM_BYTES);
    chnn_kernel<<<NCTA, NTHR, SMEM_BYTES>>>(z, mp, b0, b1, b2, W3, out);
}